// round 2
// baseline (speedup 1.0000x reference)
#include <cuda_runtime.h>
#include <math.h>

// 3D shifted-window attention, fully fused: one CTA per 4x4x4 window.
// x: (192, 64,64,64) f32; qkv_w (576,192); qkv_b (576); proj_w (192,192); proj_b (192)
// out: (192, 64,64,64) f32

#define C_DIM    192
#define THREADS  256
#define NTOK     64      // tokens per window (4*4*4)
#define NWIN     4096    // 16^3 windows
#define HEADS    6
#define HDIM     32
#define QKV_OUT  576     // 3*C

// smem layout (floats)
#define XS_OFF   0                       // x tile / attn-out: [c][t] 192*64 = 12288
#define QKV_OFF  12288                   // qkv [t][o] 64*576 = 36864 ; reused as proj-out [o][t]
#define SCR_OFF  49152                   // scratch: W tile (64*36=2304) / scores (64*64=4096)
#define SMEM_FLOATS (12288 + 36864 + 4096)
#define SMEM_BYTES  (SMEM_FLOATS * 4 + 64 * 4)   // + goff[64] ints

__global__ __launch_bounds__(THREADS, 1)
void win_attn_kernel(const float* __restrict__ x,
                     const float* __restrict__ qkv_w,
                     const float* __restrict__ qkv_b,
                     const float* __restrict__ proj_w,
                     const float* __restrict__ proj_b,
                     float* __restrict__ out)
{
    extern __shared__ float sm[];
    float* xs   = sm + XS_OFF;    // [c*64 + t]
    float* qkvs = sm + QKV_OFF;   // [t*576 + o]   (later: proj out [o*64 + t])
    float* scr  = sm + SCR_OFF;   // W tile [oo*36 + cc] / scores [i*64 + j]
    int*   goff = (int*)(sm + SMEM_FLOATS); // spatial gmem offsets per token

    const int tid = threadIdx.x;
    const int w   = blockIdx.x;
    const int wx  = w >> 8, wy = (w >> 4) & 15, wz = w & 15;

    // --- token -> global spatial offset (shift by +2 with wrap, same for read & write)
    if (tid < NTOK) {
        int tx = tid >> 4, ty = (tid >> 2) & 3, tz = tid & 3;
        int gx = (wx * 4 + tx + 2) & 63;
        int gy = (wy * 4 + ty + 2) & 63;
        int gz = (wz * 4 + tz + 2) & 63;
        goff[tid] = (gx << 12) + (gy << 6) + gz;
    }
    __syncthreads();

    // --- gather x tile: xs[c][t]
    #pragma unroll 4
    for (int idx = tid; idx < C_DIM * NTOK; idx += THREADS) {
        int c = idx >> 6, t = idx & 63;
        xs[idx] = __ldg(x + ((size_t)c << 18) + goff[t]);
    }

    const int o_thr = tid & 15;   // *4 -> output col within 64-tile
    const int t_thr = tid >> 4;   // *4 -> token row

    // =========================== QKV GEMM: qkvs[t][o] = xs^T @ Wq^T + b ==========
    for (int ot = 0; ot < 9; ++ot) {
        const int o0 = ot * 64;
        float acc[4][4] = {};
        for (int ct = 0; ct < 6; ++ct) {
            const int c0 = ct * 32;
            __syncthreads();                      // protect scr from previous readers
            // stage W tile [64 o][32 c] -> scr[oo*36 + cc] (padded)
            #pragma unroll
            for (int p = 0; p < 2; ++p) {
                int slot = tid + p * THREADS;     // 0..511
                int oo = slot >> 3, c4 = slot & 7;
                float4 wv = *reinterpret_cast<const float4*>(
                    qkv_w + (size_t)(o0 + oo) * C_DIM + c0 + c4 * 4);
                *reinterpret_cast<float4*>(&scr[oo * 36 + c4 * 4]) = wv;
            }
            __syncthreads();
            #pragma unroll
            for (int cc = 0; cc < 32; cc += 4) {
                float a[4][4], wv[4][4];
                #pragma unroll
                for (int k = 0; k < 4; ++k)
                    *reinterpret_cast<float4*>(a[k]) =
                        *reinterpret_cast<const float4*>(&xs[(c0 + cc + k) * 64 + t_thr * 4]);
                #pragma unroll
                for (int oi = 0; oi < 4; ++oi)
                    *reinterpret_cast<float4*>(wv[oi]) =
                        *reinterpret_cast<const float4*>(&scr[(o_thr * 4 + oi) * 36 + cc]);
                #pragma unroll
                for (int oi = 0; oi < 4; ++oi)
                    #pragma unroll
                    for (int k = 0; k < 4; ++k)
                        #pragma unroll
                        for (int ti = 0; ti < 4; ++ti)
                            acc[oi][ti] = fmaf(wv[oi][k], a[k][ti], acc[oi][ti]);
            }
        }
        float b0 = __ldg(qkv_b + o0 + o_thr * 4 + 0);
        float b1 = __ldg(qkv_b + o0 + o_thr * 4 + 1);
        float b2 = __ldg(qkv_b + o0 + o_thr * 4 + 2);
        float b3 = __ldg(qkv_b + o0 + o_thr * 4 + 3);
        #pragma unroll
        for (int ti = 0; ti < 4; ++ti) {
            int t = t_thr * 4 + ti;
            float4 ov = make_float4(acc[0][ti] + b0, acc[1][ti] + b1,
                                    acc[2][ti] + b2, acc[3][ti] + b3);
            *reinterpret_cast<float4*>(&qkvs[t * QKV_OUT + o0 + o_thr * 4]) = ov;
        }
    }

    // =========================== attention per head ==============================
    const float scale = rsqrtf((float)HDIM);
    float* s = scr;                                // scores [i*64 + j]
    for (int h = 0; h < HEADS; ++h) {
        const int qo = h * HDIM, ko = C_DIM + h * HDIM, vo = 2 * C_DIM + h * HDIM;
        __syncthreads();                           // scr free (prev AV done / gemm done)
        // ---- scores = q @ k^T * scale
        {
            const int i_thr = tid >> 4, j_thr = tid & 15;
            float acc[4][4] = {};
            #pragma unroll
            for (int d = 0; d < HDIM; d += 4) {
                float qv[4][4], kv[4][4];
                #pragma unroll
                for (int ii = 0; ii < 4; ++ii)
                    *reinterpret_cast<float4*>(qv[ii]) =
                        *reinterpret_cast<const float4*>(&qkvs[(i_thr * 4 + ii) * QKV_OUT + qo + d]);
                #pragma unroll
                for (int jj = 0; jj < 4; ++jj)
                    *reinterpret_cast<float4*>(kv[jj]) =
                        *reinterpret_cast<const float4*>(&qkvs[(j_thr * 4 + jj) * QKV_OUT + ko + d]);
                #pragma unroll
                for (int ii = 0; ii < 4; ++ii)
                    #pragma unroll
                    for (int jj = 0; jj < 4; ++jj)
                        #pragma unroll
                        for (int k = 0; k < 4; ++k)
                            acc[ii][jj] = fmaf(qv[ii][k], kv[jj][k], acc[ii][jj]);
            }
            #pragma unroll
            for (int ii = 0; ii < 4; ++ii) {
                float4 sv = make_float4(acc[ii][0] * scale, acc[ii][1] * scale,
                                        acc[ii][2] * scale, acc[ii][3] * scale);
                *reinterpret_cast<float4*>(&s[(i_thr * 4 + ii) * 64 + j_thr * 4]) = sv;
            }
        }
        __syncthreads();
        // ---- softmax per row (4 threads per row, quad shuffle reduce)
        {
            const int row = tid >> 2, sub = tid & 3;
            float* sr = &s[row * 64 + sub * 16];
            float v[16];
            #pragma unroll
            for (int k = 0; k < 16; k += 4)
                *reinterpret_cast<float4*>(&v[k]) = *reinterpret_cast<const float4*>(&sr[k]);
            float m = v[0];
            #pragma unroll
            for (int k = 1; k < 16; ++k) m = fmaxf(m, v[k]);
            m = fmaxf(m, __shfl_xor_sync(0xffffffffu, m, 1));
            m = fmaxf(m, __shfl_xor_sync(0xffffffffu, m, 2));
            float sum = 0.f;
            #pragma unroll
            for (int k = 0; k < 16; ++k) { v[k] = __expf(v[k] - m); sum += v[k]; }
            sum += __shfl_xor_sync(0xffffffffu, sum, 1);
            sum += __shfl_xor_sync(0xffffffffu, sum, 2);
            float inv = __frcp_rn(sum);
            #pragma unroll
            for (int k = 0; k < 16; k += 4) {
                float4 ov = make_float4(v[k] * inv, v[k + 1] * inv, v[k + 2] * inv, v[k + 3] * inv);
                *reinterpret_cast<float4*>(&sr[k]) = ov;
            }
        }
        __syncthreads();
        // ---- out = attn @ v  -> ao[c][t] stored into xs region
        {
            const int d_thr = tid & 7;   // *4
            const int i_thr = tid >> 3;  // *2
            const int i0 = i_thr * 2, d0 = d_thr * 4;
            float acc[2][4] = {};
            #pragma unroll 4
            for (int j = 0; j < 64; ++j) {
                float4 vv = *reinterpret_cast<const float4*>(&qkvs[j * QKV_OUT + vo + d0]);
                float s0 = s[i0 * 64 + j], s1 = s[(i0 + 1) * 64 + j];
                acc[0][0] = fmaf(s0, vv.x, acc[0][0]); acc[0][1] = fmaf(s0, vv.y, acc[0][1]);
                acc[0][2] = fmaf(s0, vv.z, acc[0][2]); acc[0][3] = fmaf(s0, vv.w, acc[0][3]);
                acc[1][0] = fmaf(s1, vv.x, acc[1][0]); acc[1][1] = fmaf(s1, vv.y, acc[1][1]);
                acc[1][2] = fmaf(s1, vv.z, acc[1][2]); acc[1][3] = fmaf(s1, vv.w, acc[1][3]);
            }
            #pragma unroll
            for (int ii = 0; ii < 2; ++ii)
                #pragma unroll
                for (int dd = 0; dd < 4; ++dd)
                    xs[(qo + d0 + dd) * 64 + i0 + ii] = acc[ii][dd];
        }
    }

    // =========================== proj GEMM: po[o][t] into qkvs region ============
    for (int ot = 0; ot < 3; ++ot) {
        const int o0 = ot * 64;
        float acc[4][4] = {};
        for (int ct = 0; ct < 6; ++ct) {
            const int c0 = ct * 32;
            __syncthreads();
            #pragma unroll
            for (int p = 0; p < 2; ++p) {
                int slot = tid + p * THREADS;
                int oo = slot >> 3, c4 = slot & 7;
                float4 wv = *reinterpret_cast<const float4*>(
                    proj_w + (size_t)(o0 + oo) * C_DIM + c0 + c4 * 4);
                *reinterpret_cast<float4*>(&scr[oo * 36 + c4 * 4]) = wv;
            }
            __syncthreads();
            #pragma unroll
            for (int cc = 0; cc < 32; cc += 4) {
                float a[4][4], wv[4][4];
                #pragma unroll
                for (int k = 0; k < 4; ++k)
                    *reinterpret_cast<float4*>(a[k]) =
                        *reinterpret_cast<const float4*>(&xs[(c0 + cc + k) * 64 + t_thr * 4]);
                #pragma unroll
                for (int oi = 0; oi < 4; ++oi)
                    *reinterpret_cast<float4*>(wv[oi]) =
                        *reinterpret_cast<const float4*>(&scr[(o_thr * 4 + oi) * 36 + cc]);
                #pragma unroll
                for (int oi = 0; oi < 4; ++oi)
                    #pragma unroll
                    for (int k = 0; k < 4; ++k)
                        #pragma unroll
                        for (int ti = 0; ti < 4; ++ti)
                            acc[oi][ti] = fmaf(wv[oi][k], a[k][ti], acc[oi][ti]);
            }
        }
        float b[4];
        #pragma unroll
        for (int oi = 0; oi < 4; ++oi) b[oi] = __ldg(proj_b + o0 + o_thr * 4 + oi);
        #pragma unroll
        for (int oi = 0; oi < 4; ++oi) {
            int o = o0 + o_thr * 4 + oi;
            float4 ov = make_float4(acc[oi][0] + b[oi], acc[oi][1] + b[oi],
                                    acc[oi][2] + b[oi], acc[oi][3] + b[oi]);
            *reinterpret_cast<float4*>(&qkvs[o * 64 + t_thr * 4]) = ov;
        }
    }
    __syncthreads();

    // =========================== scatter to gmem =================================
    #pragma unroll 4
    for (int idx = tid; idx < C_DIM * NTOK; idx += THREADS) {
        int c = idx >> 6, t = idx & 63;
        out[((size_t)c << 18) + goff[t]] = qkvs[idx];
    }
}

extern "C" void kernel_launch(void* const* d_in, const int* in_sizes, int n_in,
                              void* d_out, int out_size)
{
    const float* x      = (const float*)d_in[0];
    const float* qkv_w  = (const float*)d_in[1];
    const float* qkv_b  = (const float*)d_in[2];
    const float* proj_w = (const float*)d_in[3];
    const float* proj_b = (const float*)d_in[4];
    float* out = (float*)d_out;

    cudaFuncSetAttribute(win_attn_kernel,
                         cudaFuncAttributeMaxDynamicSharedMemorySize, SMEM_BYTES);
    win_attn_kernel<<<NWIN, THREADS, SMEM_BYTES>>>(x, qkv_w, qkv_b, proj_w, proj_b, out);
}

// round 4
// speedup vs baseline: 1.9322x; 1.9322x over previous
#include <cuda_runtime.h>
#include <math.h>

// 3D shifted-window attention, fused, conflict-free smem layouts.
// One CTA per 4x4x4 window; 4096 windows; 256 threads.
// x: (192,64,64,64) f32; qkv_w (576,192); qkv_b (576); proj_w (192,192); proj_b (192)

#define C_DIM    192
#define THREADS  256
#define NTOK     64
#define NWIN     4096
#define HEADS    6
#define HDIM     32
#define QKV_OUT  576

// pre-transposed weights [c][o]
__device__ float g_wt_qkv[C_DIM * QKV_OUT];   // stride 576
__device__ float g_wt_proj[C_DIM * C_DIM];    // stride 192

// smem layout (floats)
#define XS_OFF   0                    // xs [c][t]        192*64 = 12288
#define QK_OFF   12288                // qkv [o][t]       576*64 = 36864 ; later proj-out [o][t]
#define ST_OFF   49152                // sT  [j][i]        64*64 =  4096
#define WT_OFF   53248                // W tile [c][o]     32*64 =  2048
#define RED_OFF  55296                // partials [4][64]          =   256
#define GOFF_OFF 55552                // token gmem offsets (ints) =    64
#define SMEM_FLOATS 55616
#define SMEM_BYTES  (SMEM_FLOATS * 4)

__global__ void transpose_weights(const float* __restrict__ qkv_w,
                                  const float* __restrict__ proj_w)
{
    int i = blockIdx.x * blockDim.x + threadIdx.x;
    if (i < C_DIM * QKV_OUT) {
        int c = i / QKV_OUT, o = i % QKV_OUT;
        g_wt_qkv[i] = qkv_w[o * C_DIM + c];
    } else {
        int j = i - C_DIM * QKV_OUT;
        if (j < C_DIM * C_DIM) {
            int c = j / C_DIM, o = j % C_DIM;
            g_wt_proj[j] = proj_w[o * C_DIM + c];
        }
    }
}

__global__ __launch_bounds__(THREADS, 1)
void win_attn_kernel(const float* __restrict__ x,
                     const float* __restrict__ qkv_b,
                     const float* __restrict__ proj_b,
                     float* __restrict__ out)
{
    extern __shared__ float sm[];
    float* xs   = sm + XS_OFF;
    float* qkvs = sm + QK_OFF;
    float* st   = sm + ST_OFF;
    float* wt   = sm + WT_OFF;
    float* red  = sm + RED_OFF;
    int*   goff = (int*)(sm + GOFF_OFF);

    const int tid = threadIdx.x;
    const int w   = blockIdx.x;
    const int wx  = w >> 8, wy = (w >> 4) & 15, wz = w & 15;

    if (tid < NTOK) {
        int tx = tid >> 4, ty = (tid >> 2) & 3, tz = tid & 3;
        int gx = (wx * 4 + tx + 2) & 63;
        int gy = (wy * 4 + ty + 2) & 63;
        int gz = (wz * 4 + tz + 2) & 63;
        goff[tid] = (gx << 12) + (gy << 6) + gz;
    }
    __syncthreads();

    // gather x tile: xs[c*64 + t]
    #pragma unroll 4
    for (int idx = tid; idx < C_DIM * NTOK; idx += THREADS) {
        int c = idx >> 6, t = idx & 63;
        xs[idx] = __ldg(x + ((size_t)c << 18) + goff[t]);
    }

    const int t_thr = tid & 15;   // token group (lane-contiguous)
    const int o_thr = tid >> 4;   // output group (warp-broadcast)

    // ================= QKV GEMM: qkvs[o][t] = Wt^T-style, conflict-free =======
    for (int ot = 0; ot < 9; ++ot) {
        const int o0 = ot * 64;
        float acc[4][4] = {};
        for (int ct = 0; ct < 6; ++ct) {
            const int c0 = ct * 32;
            __syncthreads();
            // stage Wt tile [32 c][64 o] -> wt (rows stride 64, fully contiguous)
            #pragma unroll
            for (int p = 0; p < 2; ++p) {
                int s = tid + p * THREADS;         // 0..511
                int cr = s >> 4, o4 = (s & 15) * 4;
                *reinterpret_cast<float4*>(&wt[cr * 64 + o4]) =
                    *reinterpret_cast<const float4*>(
                        &g_wt_qkv[(size_t)(c0 + cr) * QKV_OUT + o0 + o4]);
            }
            __syncthreads();
            #pragma unroll 8
            for (int k = 0; k < 32; ++k) {
                float4 av = *reinterpret_cast<const float4*>(&xs[(c0 + k) * 64 + t_thr * 4]);
                float4 wv = *reinterpret_cast<const float4*>(&wt[k * 64 + o_thr * 4]);
                float a4[4] = {av.x, av.y, av.z, av.w};
                float w4[4] = {wv.x, wv.y, wv.z, wv.w};
                #pragma unroll
                for (int oi = 0; oi < 4; ++oi)
                    #pragma unroll
                    for (int ti = 0; ti < 4; ++ti)
                        acc[oi][ti] = fmaf(w4[oi], a4[ti], acc[oi][ti]);
            }
        }
        float4 bv = __ldg(reinterpret_cast<const float4*>(qkv_b + o0 + o_thr * 4));
        float b4[4] = {bv.x, bv.y, bv.z, bv.w};
        #pragma unroll
        for (int oi = 0; oi < 4; ++oi) {
            float4 ov = make_float4(acc[oi][0] + b4[oi], acc[oi][1] + b4[oi],
                                    acc[oi][2] + b4[oi], acc[oi][3] + b4[oi]);
            *reinterpret_cast<float4*>(&qkvs[(o0 + o_thr * 4 + oi) * 64 + t_thr * 4]) = ov;
        }
    }

    // ================= attention per head ====================================
    const float scale = 0.17677669529663688f;  // 1/sqrt(32)
    for (int h = 0; h < HEADS; ++h) {
        const int qo = h * HDIM, ko = C_DIM + h * HDIM, vo = 2 * C_DIM + h * HDIM;
        __syncthreads();   // qkvs ready / sT free from previous head

        // ---- scores (outer product over d): sT[j][i] = (q_i . k_j) * scale
        {
            const int i_thr = tid & 15, j_thr = tid >> 4;
            float acc[4][4] = {};   // [ii][jj]
            #pragma unroll 8
            for (int d = 0; d < HDIM; ++d) {
                float4 qv = *reinterpret_cast<const float4*>(&qkvs[(qo + d) * 64 + i_thr * 4]);
                float4 kv = *reinterpret_cast<const float4*>(&qkvs[(ko + d) * 64 + j_thr * 4]);
                float q4[4] = {qv.x, qv.y, qv.z, qv.w};
                float k4[4] = {kv.x, kv.y, kv.z, kv.w};
                #pragma unroll
                for (int ii = 0; ii < 4; ++ii)
                    #pragma unroll
                    for (int jj = 0; jj < 4; ++jj)
                        acc[ii][jj] = fmaf(q4[ii], k4[jj], acc[ii][jj]);
            }
            #pragma unroll
            for (int jj = 0; jj < 4; ++jj) {
                float4 sv = make_float4(acc[0][jj] * scale, acc[1][jj] * scale,
                                        acc[2][jj] * scale, acc[3][jj] * scale);
                *reinterpret_cast<float4*>(&st[(j_thr * 4 + jj) * 64 + i_thr * 4]) = sv;
            }
        }
        __syncthreads();

        // ---- softmax over columns of sT (lane-contiguous), 4 partials + combine
        const int col = tid & 63, sub = tid >> 6;
        {
            float part = -1e30f;
            #pragma unroll
            for (int jj = 0; jj < 16; ++jj)
                part = fmaxf(part, st[(sub * 16 + jj) * 64 + col]);
            red[sub * 64 + col] = part;
        }
        __syncthreads();
        {
            float m = fmaxf(fmaxf(red[col], red[64 + col]),
                            fmaxf(red[128 + col], red[192 + col]));
            __syncthreads();   // all partial-max reads done before red reused for sums
            float sum = 0.f;
            #pragma unroll
            for (int jj = 0; jj < 16; ++jj) {
                int a = (sub * 16 + jj) * 64 + col;
                float e = __expf(st[a] - m);
                st[a] = e;
                sum += e;
            }
            red[sub * 64 + col] = sum;
        }
        __syncthreads();

        // ---- AV: xs[qo+d][i] = (sum_j e[j][i] * v[d][j]) / rowsum(i)
        {
            const int i_thr = tid & 15, d_thr = tid >> 4;
            float acc[2][4] = {};
            #pragma unroll 4
            for (int j0 = 0; j0 < 64; j0 += 4) {
                float va[4], vb[4];
                *reinterpret_cast<float4*>(va) =
                    *reinterpret_cast<const float4*>(&qkvs[(vo + d_thr) * 64 + j0]);
                *reinterpret_cast<float4*>(vb) =
                    *reinterpret_cast<const float4*>(&qkvs[(vo + d_thr + 16) * 64 + j0]);
                #pragma unroll
                for (int jj = 0; jj < 4; ++jj) {
                    float4 sv = *reinterpret_cast<const float4*>(&st[(j0 + jj) * 64 + i_thr * 4]);
                    acc[0][0] = fmaf(va[jj], sv.x, acc[0][0]);
                    acc[0][1] = fmaf(va[jj], sv.y, acc[0][1]);
                    acc[0][2] = fmaf(va[jj], sv.z, acc[0][2]);
                    acc[0][3] = fmaf(va[jj], sv.w, acc[0][3]);
                    acc[1][0] = fmaf(vb[jj], sv.x, acc[1][0]);
                    acc[1][1] = fmaf(vb[jj], sv.y, acc[1][1]);
                    acc[1][2] = fmaf(vb[jj], sv.z, acc[1][2]);
                    acc[1][3] = fmaf(vb[jj], sv.w, acc[1][3]);
                }
            }
            // inverse row sums for i = i_thr*4 .. +3
            float4 r0 = *reinterpret_cast<const float4*>(&red[i_thr * 4]);
            float4 r1 = *reinterpret_cast<const float4*>(&red[64 + i_thr * 4]);
            float4 r2 = *reinterpret_cast<const float4*>(&red[128 + i_thr * 4]);
            float4 r3 = *reinterpret_cast<const float4*>(&red[192 + i_thr * 4]);
            float inv[4];
            inv[0] = __frcp_rn(r0.x + r1.x + r2.x + r3.x);
            inv[1] = __frcp_rn(r0.y + r1.y + r2.y + r3.y);
            inv[2] = __frcp_rn(r0.z + r1.z + r2.z + r3.z);
            inv[3] = __frcp_rn(r0.w + r1.w + r2.w + r3.w);
            #pragma unroll
            for (int dd = 0; dd < 2; ++dd) {
                float4 ov = make_float4(acc[dd][0] * inv[0], acc[dd][1] * inv[1],
                                        acc[dd][2] * inv[2], acc[dd][3] * inv[3]);
                *reinterpret_cast<float4*>(&xs[(qo + d_thr + 16 * dd) * 64 + i_thr * 4]) = ov;
            }
        }
    }

    // ================= proj GEMM: po[o][t] into qkvs region ===================
    for (int ot = 0; ot < 3; ++ot) {
        const int o0 = ot * 64;
        float acc[4][4] = {};
        for (int ct = 0; ct < 6; ++ct) {
            const int c0 = ct * 32;
            __syncthreads();
            #pragma unroll
            for (int p = 0; p < 2; ++p) {
                int s = tid + p * THREADS;
                int cr = s >> 4, o4 = (s & 15) * 4;
                *reinterpret_cast<float4*>(&wt[cr * 64 + o4]) =
                    *reinterpret_cast<const float4*>(
                        &g_wt_proj[(size_t)(c0 + cr) * C_DIM + o0 + o4]);
            }
            __syncthreads();
            #pragma unroll 8
            for (int k = 0; k < 32; ++k) {
                float4 av = *reinterpret_cast<const float4*>(&xs[(c0 + k) * 64 + t_thr * 4]);
                float4 wv = *reinterpret_cast<const float4*>(&wt[k * 64 + o_thr * 4]);
                float a4[4] = {av.x, av.y, av.z, av.w};
                float w4[4] = {wv.x, wv.y, wv.z, wv.w};
                #pragma unroll
                for (int oi = 0; oi < 4; ++oi)
                    #pragma unroll
                    for (int ti = 0; ti < 4; ++ti)
                        acc[oi][ti] = fmaf(w4[oi], a4[ti], acc[oi][ti]);
            }
        }
        float4 bv = __ldg(reinterpret_cast<const float4*>(proj_b + o0 + o_thr * 4));
        float b4[4] = {bv.x, bv.y, bv.z, bv.w};
        #pragma unroll
        for (int oi = 0; oi < 4; ++oi) {
            float4 ov = make_float4(acc[oi][0] + b4[oi], acc[oi][1] + b4[oi],
                                    acc[oi][2] + b4[oi], acc[oi][3] + b4[oi]);
            *reinterpret_cast<float4*>(&qkvs[(o0 + o_thr * 4 + oi) * 64 + t_thr * 4]) = ov;
        }
    }
    __syncthreads();

    // ================= scatter ===============================================
    #pragma unroll 4
    for (int idx = tid; idx < C_DIM * NTOK; idx += THREADS) {
        int c = idx >> 6, t = idx & 63;
        out[((size_t)c << 18) + goff[t]] = qkvs[idx];
    }
}

extern "C" void kernel_launch(void* const* d_in, const int* in_sizes, int n_in,
                              void* d_out, int out_size)
{
    const float* x      = (const float*)d_in[0];
    const float* qkv_w  = (const float*)d_in[1];
    const float* qkv_b  = (const float*)d_in[2];
    const float* proj_w = (const float*)d_in[3];
    const float* proj_b = (const float*)d_in[4];
    float* out = (float*)d_out;

    int n_t = C_DIM * QKV_OUT + C_DIM * C_DIM;           // 147456
    transpose_weights<<<(n_t + 255) / 256, 256>>>(qkv_w, proj_w);

    cudaFuncSetAttribute(win_attn_kernel,
                         cudaFuncAttributeMaxDynamicSharedMemorySize, SMEM_BYTES);
    win_attn_kernel<<<NWIN, THREADS, SMEM_BYTES>>>(x, qkv_b, proj_b, out);
}

// round 8
// speedup vs baseline: 2.0659x; 1.0692x over previous
#include <cuda_runtime.h>
#include <math.h>

// 3D shifted-window attention, fused, conflict-free smem, 512 threads/CTA.
// One CTA per 4x4x4 window; 4096 windows.

#define C_DIM    192
#define THREADS  512
#define NTOK     64
#define NWIN     4096
#define HEADS    6
#define HDIM     32
#define QKV_OUT  576

// pre-transposed weights [c][o]
__device__ float g_wt_qkv[C_DIM * QKV_OUT];   // stride 576
__device__ float g_wt_proj[C_DIM * C_DIM];    // stride 192

// smem layout (floats)
#define XS_OFF   0                    // xs [c][t]     192*64 = 12288
#define QK_OFF   12288                // qkv [o][t]    576*64 = 36864 ; later proj-out
#define ST_OFF   49152                // sT [j][i]      64*64 =  4096
#define WT_OFF   53248                // W tile [32][128]     =  4096
#define RED_OFF  57344                // partials [8][64]     =   512
#define SMEM_FLOATS 57856
#define SMEM_BYTES  (SMEM_FLOATS * 4 + 64 * 4)   // + goff[64]

__global__ void transpose_weights(const float* __restrict__ qkv_w,
                                  const float* __restrict__ proj_w)
{
    int i = blockIdx.x * blockDim.x + threadIdx.x;
    if (i < C_DIM * QKV_OUT) {
        int c = i / QKV_OUT, o = i % QKV_OUT;
        g_wt_qkv[i] = qkv_w[o * C_DIM + c];
    } else {
        int j = i - C_DIM * QKV_OUT;
        if (j < C_DIM * C_DIM) {
            int c = j / C_DIM, o = j % C_DIM;
            g_wt_proj[j] = proj_w[o * C_DIM + c];
        }
    }
}

// 128-wide output tile GEMM: dst[o][t], K=192, micro 4o x 4t
__device__ __forceinline__ void gemm_tile128(
    const float* __restrict__ gw, int gw_stride, int o0,
    const float* __restrict__ src, float* wt,
    const float* __restrict__ bias, float* dst, int tid)
{
    const int o_thr = tid >> 4;   // 0..31
    const int t_thr = tid & 15;
    float acc[4][4] = {};
    for (int ct = 0; ct < 6; ++ct) {
        const int c0 = ct * 32;
        __syncthreads();
        #pragma unroll
        for (int p = 0; p < 2; ++p) {
            int s = tid + p * THREADS;              // 0..1023
            int cr = s >> 5, o4 = (s & 31) * 4;
            *reinterpret_cast<float4*>(&wt[cr * 128 + o4]) =
                *reinterpret_cast<const float4*>(&gw[(size_t)(c0 + cr) * gw_stride + o0 + o4]);
        }
        __syncthreads();
        #pragma unroll 8
        for (int k = 0; k < 32; ++k) {
            float4 av = *reinterpret_cast<const float4*>(&src[(c0 + k) * 64 + t_thr * 4]);
            float4 wv = *reinterpret_cast<const float4*>(&wt[k * 128 + o_thr * 4]);
            float a4[4] = {av.x, av.y, av.z, av.w};
            float w4[4] = {wv.x, wv.y, wv.z, wv.w};
            #pragma unroll
            for (int oi = 0; oi < 4; ++oi)
                #pragma unroll
                for (int ti = 0; ti < 4; ++ti)
                    acc[oi][ti] = fmaf(w4[oi], a4[ti], acc[oi][ti]);
        }
    }
    float4 bv = __ldg(reinterpret_cast<const float4*>(bias + o0 + o_thr * 4));
    float b4[4] = {bv.x, bv.y, bv.z, bv.w};
    #pragma unroll
    for (int oi = 0; oi < 4; ++oi) {
        float4 ov = make_float4(acc[oi][0] + b4[oi], acc[oi][1] + b4[oi],
                                acc[oi][2] + b4[oi], acc[oi][3] + b4[oi]);
        *reinterpret_cast<float4*>(&dst[(o0 + o_thr * 4 + oi) * 64 + t_thr * 4]) = ov;
    }
}

// 64-wide output tail tile GEMM (micro 2o x 4t)
__device__ __forceinline__ void gemm_tile64(
    const float* __restrict__ gw, int gw_stride, int o0,
    const float* __restrict__ src, float* wt,
    const float* __restrict__ bias, float* dst, int tid)
{
    const int o_thr = tid >> 4;   // 0..31, *2
    const int t_thr = tid & 15;
    float acc[2][4] = {};
    for (int ct = 0; ct < 6; ++ct) {
        const int c0 = ct * 32;
        __syncthreads();
        {
            int cr = tid >> 4, o4 = (tid & 15) * 4;
            *reinterpret_cast<float4*>(&wt[cr * 64 + o4]) =
                *reinterpret_cast<const float4*>(&gw[(size_t)(c0 + cr) * gw_stride + o0 + o4]);
        }
        __syncthreads();
        #pragma unroll 8
        for (int k = 0; k < 32; ++k) {
            float4 av = *reinterpret_cast<const float4*>(&src[(c0 + k) * 64 + t_thr * 4]);
            float2 wv = *reinterpret_cast<const float2*>(&wt[k * 64 + o_thr * 2]);
            float a4[4] = {av.x, av.y, av.z, av.w};
            #pragma unroll
            for (int ti = 0; ti < 4; ++ti) {
                acc[0][ti] = fmaf(wv.x, a4[ti], acc[0][ti]);
                acc[1][ti] = fmaf(wv.y, a4[ti], acc[1][ti]);
            }
        }
    }
    float2 bv = __ldg(reinterpret_cast<const float2*>(bias + o0 + o_thr * 2));
    float b2[2] = {bv.x, bv.y};
    #pragma unroll
    for (int oi = 0; oi < 2; ++oi) {
        float4 ov = make_float4(acc[oi][0] + b2[oi], acc[oi][1] + b2[oi],
                                acc[oi][2] + b2[oi], acc[oi][3] + b2[oi]);
        *reinterpret_cast<float4*>(&dst[(o0 + o_thr * 2 + oi) * 64 + t_thr * 4]) = ov;
    }
}

__global__ __launch_bounds__(THREADS, 1)
void win_attn_kernel(const float* __restrict__ x,
                     const float* __restrict__ qkv_b,
                     const float* __restrict__ proj_b,
                     float* __restrict__ out)
{
    extern __shared__ float sm[];
    float* xs   = sm + XS_OFF;
    float* qkvs = sm + QK_OFF;
    float* st   = sm + ST_OFF;
    float* wt   = sm + WT_OFF;
    float* red  = sm + RED_OFF;
    int*   goff = (int*)(sm + SMEM_FLOATS);

    const int tid = threadIdx.x;
    const int w   = blockIdx.x;
    const int wx  = w >> 8, wy = (w >> 4) & 15, wz = w & 15;

    if (tid < NTOK) {
        int tx = tid >> 4, ty = (tid >> 2) & 3, tz = tid & 3;
        int gx = (wx * 4 + tx + 2) & 63;
        int gy = (wy * 4 + ty + 2) & 63;
        int gz = (wz * 4 + tz + 2) & 63;
        goff[tid] = (gx << 12) + (gy << 6) + gz;
    }
    __syncthreads();

    // gather x tile: xs[c*64 + t]
    #pragma unroll 4
    for (int idx = tid; idx < C_DIM * NTOK; idx += THREADS) {
        int c = idx >> 6, t = idx & 63;
        xs[idx] = __ldg(x + ((size_t)c << 18) + goff[t]);
    }
    // (first __syncthreads inside gemm_tile128 covers the gather)

    // ================= QKV GEMM: qkvs[o][t], o in [0,576) ====================
    #pragma unroll 1
    for (int ot = 0; ot < 4; ++ot)
        gemm_tile128(g_wt_qkv, QKV_OUT, ot * 128, xs, wt, qkv_b, qkvs, tid);
    gemm_tile64(g_wt_qkv, QKV_OUT, 512, xs, wt, qkv_b, qkvs, tid);

    // ================= attention per head ====================================
    const float scale = 0.17677669529663688f;  // 1/sqrt(32)
    #pragma unroll 1
    for (int h = 0; h < HEADS; ++h) {
        const int qo = h * HDIM, ko = C_DIM + h * HDIM, vo = 2 * C_DIM + h * HDIM;
        __syncthreads();

        // ---- scores: sT[j][i] = (q_i . k_j) * scale   (micro 4i x 2j)
        {
            const int i_thr = tid & 15, j_thr = tid >> 4;  // j_thr 0..31 (*2)
            float acc[4][2] = {};
            #pragma unroll 8
            for (int d = 0; d < HDIM; ++d) {
                float4 qv = *reinterpret_cast<const float4*>(&qkvs[(qo + d) * 64 + i_thr * 4]);
                float2 kv = *reinterpret_cast<const float2*>(&qkvs[(ko + d) * 64 + j_thr * 2]);
                float q4[4] = {qv.x, qv.y, qv.z, qv.w};
                #pragma unroll
                for (int ii = 0; ii < 4; ++ii) {
                    acc[ii][0] = fmaf(q4[ii], kv.x, acc[ii][0]);
                    acc[ii][1] = fmaf(q4[ii], kv.y, acc[ii][1]);
                }
            }
            #pragma unroll
            for (int jj = 0; jj < 2; ++jj) {
                float4 sv = make_float4(acc[0][jj] * scale, acc[1][jj] * scale,
                                        acc[2][jj] * scale, acc[3][jj] * scale);
                *reinterpret_cast<float4*>(&st[(j_thr * 2 + jj) * 64 + i_thr * 4]) = sv;
            }
        }
        __syncthreads();

        // ---- softmax over columns of sT: 8 partials per column
        const int col = tid & 63, sub = tid >> 6;   // sub 0..7, 8 rows each
        {
            float part = -1e30f;
            #pragma unroll
            for (int jj = 0; jj < 8; ++jj)
                part = fmaxf(part, st[(sub * 8 + jj) * 64 + col]);
            red[sub * 64 + col] = part;
        }
        __syncthreads();
        {
            float m = red[col];
            #pragma unroll
            for (int r = 1; r < 8; ++r) m = fmaxf(m, red[r * 64 + col]);
            __syncthreads();   // all partial-max reads done before red reused
            float sum = 0.f;
            #pragma unroll
            for (int jj = 0; jj < 8; ++jj) {
                int a = (sub * 8 + jj) * 64 + col;
                float e = __expf(st[a] - m);
                st[a] = e;
                sum += e;
            }
            red[sub * 64 + col] = sum;
        }
        __syncthreads();
        // combine partial sums -> red[0..63] = 1/rowsum
        if (tid < NTOK) {
            float tot = red[tid];
            #pragma unroll
            for (int r = 1; r < 8; ++r) tot += red[r * 64 + tid];
            red[tid] = __frcp_rn(tot);
        }
        __syncthreads();

        // ---- AV: xs[qo+d][i] = (sum_j e[j][i] * v[d][j]) * inv(i)
        {
            const int i_thr = tid & 15, d_thr = tid >> 4;   // d 0..31
            float acc[4] = {};
            #pragma unroll 4
            for (int j0 = 0; j0 < 64; j0 += 4) {
                float4 vv = *reinterpret_cast<const float4*>(&qkvs[(vo + d_thr) * 64 + j0]);
                float v4[4] = {vv.x, vv.y, vv.z, vv.w};
                #pragma unroll
                for (int jj = 0; jj < 4; ++jj) {
                    float4 sv = *reinterpret_cast<const float4*>(&st[(j0 + jj) * 64 + i_thr * 4]);
                    acc[0] = fmaf(v4[jj], sv.x, acc[0]);
                    acc[1] = fmaf(v4[jj], sv.y, acc[1]);
                    acc[2] = fmaf(v4[jj], sv.z, acc[2]);
                    acc[3] = fmaf(v4[jj], sv.w, acc[3]);
                }
            }
            float4 iv = *reinterpret_cast<const float4*>(&red[i_thr * 4]);
            float4 ov = make_float4(acc[0] * iv.x, acc[1] * iv.y,
                                    acc[2] * iv.z, acc[3] * iv.w);
            *reinterpret_cast<float4*>(&xs[(qo + d_thr) * 64 + i_thr * 4]) = ov;
        }
    }

    // ================= proj GEMM: po[o][t] into qkvs region ===================
    gemm_tile128(g_wt_proj, C_DIM, 0,   xs, wt, proj_b, qkvs, tid);
    gemm_tile64 (g_wt_proj, C_DIM, 128, xs, wt, proj_b, qkvs, tid);
    __syncthreads();

    // ================= scatter ===============================================
    #pragma unroll 4
    for (int idx = tid; idx < C_DIM * NTOK; idx += THREADS) {
        int c = idx >> 6, t = idx & 63;
        out[((size_t)c << 18) + goff[t]] = qkvs[idx];
    }
}

extern "C" void kernel_launch(void* const* d_in, const int* in_sizes, int n_in,
                              void* d_out, int out_size)
{
    const float* x      = (const float*)d_in[0];
    const float* qkv_w  = (const float*)d_in[1];
    const float* qkv_b  = (const float*)d_in[2];
    const float* proj_w = (const float*)d_in[3];
    const float* proj_b = (const float*)d_in[4];
    float* out = (float*)d_out;

    int n_t = C_DIM * QKV_OUT + C_DIM * C_DIM;
    transpose_weights<<<(n_t + 255) / 256, 256>>>(qkv_w, proj_w);

    cudaFuncSetAttribute(win_attn_kernel,
                         cudaFuncAttributeMaxDynamicSharedMemorySize, SMEM_BYTES);
    win_attn_kernel<<<NWIN, THREADS, SMEM_BYTES>>>(x, qkv_b, proj_b, out);
}